// round 11
// baseline (speedup 1.0000x reference)
#include <cuda_runtime.h>

#define N 4096
#define T 128                 // tiles of 32 agents
#define NUNITS 8256           // T*(T+1)/2, unordered tile pairs incl diagonal
#define NBLK_A 152
#define WARPS_A 32
#define NWARPS_A (NBLK_A * WARPS_A)   // 4864

#define PED_SPEED  1.34f
#define K_GAIN     2.0f
#define ALPHA      10.66f
#define PED_RADIUS 0.3f
#define PED_MASS   60.0f
#define BETTA      0.71f
#define DT         0.4f
#define COST_A     1.0f
#define COST_B     1.0f
#define COST_E     1.0f
#define EPS        1e-8f

#define LOG2E      1.4426950408889634f
#define LOG2_ALPHA 3.4140815f

// Scratch: part[a][o][lane] = repulsive force on agent a*32+lane contributed by
// the unit pairing tile a with tile o. Every slot written exactly once per launch.
__device__ float2 g_part[T * T * 32];

__device__ __forceinline__ float fast_rsqrt(float x) {
    float y; asm("rsqrt.approx.ftz.f32 %0, %1;" : "=f"(y) : "f"(x)); return y;
}
__device__ __forceinline__ float fast_ex2(float x) {
    float y; asm("ex2.approx.ftz.f32 %0, %1;" : "=f"(y) : "f"(x)); return y;
}

__device__ __forceinline__ int tri_offset(int a) {   // first unit index of row a
    return 128 * a - (a * (a - 1)) / 2;
}

// ---------------- Phase A: symmetric pairwise repulsion ----------------
__global__ __launch_bounds__(1024, 1)
void phaseA_kernel(const float4* __restrict__ state)
{
    __shared__ float2 spos[N];   // 32 KB

    const int tid  = threadIdx.x;
    const int warp = tid >> 5;
    const int lane = tid & 31;

    #pragma unroll
    for (int k = 0; k < N / 1024; ++k) {
        const int j = tid + k * 1024;
        const float4 s = state[j];
        spos[j] = make_float2(s.x, s.y);
    }
    __syncthreads();

    const float cA  = -(1.0f / BETTA) * LOG2E;
    const float cB2 = (2.0f * PED_RADIUS / BETTA) * LOG2E + LOG2_ALPHA;

    // Transposed warp id: spreads the 2-unit warps evenly across blocks/SMs.
    const int g = warp * NBLK_A + blockIdx.x;

    #pragma unroll
    for (int rep = 0; rep < 2; ++rep) {
        const int u = g + rep * NWARPS_A;
        if (u >= NUNITS) break;

        // Triangular decode: u -> (a, b), a <= b
        int a = (int)(128.5f - sqrtf(fmaf(-2.0f, (float)u, 128.5f * 128.5f)));
        while (tri_offset(a + 1) <= u) ++a;
        while (tri_offset(a) > u) --a;
        const int b = a + (u - tri_offset(a));

        const float2 pa = spos[a * 32 + lane];
        const int bbase = b * 32;

        if (a == b) {
            // Diagonal: one-sided 32x32 (self-step contributes exactly 0)
            float fax = 0.0f, fay = 0.0f;
            #pragma unroll 4
            for (int k = 0; k < 32; ++k) {
                const int m = (lane - k) & 31;
                const float2 pb = spos[bbase + m];
                const float dx = pa.x - pb.x;
                const float dy = pa.y - pb.y;
                const float d2 = fmaf(dx, dx, fmaf(dy, dy, EPS));
                const float rs = fast_rsqrt(d2);
                const float d  = d2 * rs;
                const float e  = fast_ex2(fmaf(d, cA, cB2));
                const float c  = e * rs;
                fax = fmaf(c, dx, fax);
                fay = fmaf(c, dy, fay);
            }
            g_part[(a * T + b) * 32 + lane] = make_float2(fax, fay);
        } else {
            // Off-diagonal: symmetric. fa accumulates per-lane (tile a);
            // gb rotates with the b-agent it currently represents.
            float fax = 0.0f, fay = 0.0f;
            float gbx = 0.0f, gby = 0.0f;
            const int src = (lane + 31) & 31;   // receive from lane-1
            #pragma unroll 4
            for (int k = 0; k < 32; ++k) {
                const int m = (lane - k) & 31;       // b-agent handled this step
                const float2 pb = spos[bbase + m];
                const float dx = pa.x - pb.x;
                const float dy = pa.y - pb.y;
                const float d2 = fmaf(dx, dx, fmaf(dy, dy, EPS));
                const float rs = fast_rsqrt(d2);
                const float d  = d2 * rs;
                const float e  = fast_ex2(fmaf(d, cA, cB2));
                const float c  = e * rs;
                fax = fmaf(c, dx, fax);
                fay = fmaf(c, dy, fay);
                gbx = fmaf(-c, dx, gbx);             // force on b-agent m
                gby = fmaf(-c, dy, gby);
                // rotate gb so lane l next holds agent (l-(k+1))&31
                gbx = __shfl_sync(0xffffffffu, gbx, src);
                gby = __shfl_sync(0xffffffffu, gby, src);
            }
            // after 32 rotations gb is home: lane l holds agent b*32+l
            g_part[(a * T + b) * 32 + lane] = make_float2(fax, fay);
            g_part[(b * T + a) * 32 + lane] = make_float2(gbx, gby);
        }
    }
}

// ---------------- Phase B: reduce partials + attraction + propagate + cost ----
__global__ __launch_bounds__(128)
void phaseB_kernel(const float4* __restrict__ state,
                   const float*  __restrict__ cost_in,
                   const float2* __restrict__ goals,
                   const float*  __restrict__ robot_init_pose,
                   const float4* __restrict__ observed,
                   float4* __restrict__ out,
                   float*  __restrict__ cost_out)
{
    const int i = blockIdx.x * blockDim.x + threadIdx.x;   // agent id
    if (i >= N) return;
    const int t = i >> 5;
    const int l = i & 31;

    const float cA  = -(1.0f / BETTA) * LOG2E;  (void)cA;

    // own repulsive force: fixed-order sum over the 128 tile partials
    float fx = 0.0f, fy = 0.0f;
    #pragma unroll 8
    for (int o = 0; o < T; ++o) {
        const float2 p = g_part[(t * T + o) * 32 + l];
        fx += p.x; fy += p.y;
    }

    // robot repulsive force (redundant per thread; broadcast L2 reads)
    float Rfx = 0.0f, Rfy = 0.0f;
    #pragma unroll 8
    for (int o = 0; o < T; ++o) {
        const float2 p = g_part[o * 32];       // part[0][o][0]
        Rfx += p.x; Rfy += p.y;
    }

    // robot new pose
    const float4 s0 = state[0];
    const float2 g0 = goals[0];
    float r0x, r0y;
    {
        const float tgx = g0.x - s0.x;
        const float tgy = g0.y - s0.y;
        const float inv_gd = fast_rsqrt(fmaf(tgx, tgx, fmaf(tgy, tgy, EPS)));
        const float Fx = Rfx + K_GAIN * PED_MASS * (PED_SPEED * tgx * inv_gd - s0.z);
        const float Fy = Rfy + K_GAIN * PED_MASS * (PED_SPEED * tgy * inv_gd - s0.w);
        float vnx = fmaf(Fx, DT / PED_MASS, s0.z);
        float vny = fmaf(Fy, DT / PED_MASS, s0.w);
        const float spd = sqrtf(fmaf(vnx, vnx, fmaf(vny, vny, EPS)));
        const float sc = fminf(1.0f, PED_SPEED / spd);
        vnx *= sc; vny *= sc;
        r0x = fmaf(vnx, DT, s0.x);
        r0y = fmaf(vny, DT, s0.y);
    }

    // this agent: attraction + propagation
    const float4 s = state[i];
    const float2 g = goals[i];
    const float tgx = g.x - s.x;
    const float tgy = g.y - s.y;
    const float inv_gd = fast_rsqrt(fmaf(tgx, tgx, fmaf(tgy, tgy, EPS)));
    const float Fx = fx + K_GAIN * PED_MASS * (PED_SPEED * tgx * inv_gd - s.z);
    const float Fy = fy + K_GAIN * PED_MASS * (PED_SPEED * tgy * inv_gd - s.w);

    float vnx = fmaf(Fx, DT / PED_MASS, s.z);
    float vny = fmaf(Fy, DT / PED_MASS, s.w);
    const float spd = sqrtf(fmaf(vnx, vnx, fmaf(vny, vny, EPS)));
    const float sc = fminf(1.0f, PED_SPEED / spd);
    vnx *= sc; vny *= sc;
    const float pnx = fmaf(vnx, DT, s.x);
    const float pny = fmaf(vny, DT, s.y);

    out[i] = make_float4(pnx, pny, vnx, vny);

    // cost
    const float ripx = robot_init_pose[0];
    const float ripy = robot_init_pose[1];
    const float gvx = g0.x - ripx;
    const float gvy = g0.y - ripy;
    const float gnorm = sqrtf(gvx * gvx + gvy * gvy) + EPS;
    const float pg = ((r0x - ripx) * gvx + (r0y - ripy) * gvy) / gnorm;

    const float ddx = pnx - r0x;
    const float ddy = pny - r0y;
    const float dist = sqrtf(fmaf(ddx, ddx, fmaf(ddy, ddy, EPS)));
    const float blame = COST_B * fast_ex2(-dist * (LOG2E / COST_E));

    const float4 obs = observed[i];
    const float ox = pnx - obs.x;
    const float oy = pny - obs.y;
    const float dev = fmaf(ox, ox, oy * oy);

    cost_out[i] = cost_in[i] + (-COST_A * pg + blame + dev);
}

extern "C" void kernel_launch(void* const* d_in, const int* in_sizes, int n_in,
                              void* d_out, int out_size)
{
    const float4* state    = (const float4*)d_in[0];
    const float*  cost_in  = (const float*) d_in[1];
    const float2* goals    = (const float2*)d_in[2];
    const float*  rip      = (const float*) d_in[3];
    const float4* observed = (const float4*)d_in[4];

    float4* out_state = (float4*)d_out;
    float*  cost_out  = (float*)d_out + (size_t)N * 4;

    phaseA_kernel<<<NBLK_A, 1024>>>(state);
    phaseB_kernel<<<N / 128, 128>>>(state, cost_in, goals, rip, observed,
                                    out_state, cost_out);
}

// round 12
// speedup vs baseline: 1.2120x; 1.2120x over previous
#include <cuda_runtime.h>

#define N 4096
#define T 128                 // tiles of 32 agents
#define NUNITS 8256           // T*(T+1)/2, unordered tile pairs incl diagonal
#define NBLK_A 152
#define WARPS_A 32
#define NWARPS_A (NBLK_A * WARPS_A)   // 4864

#define PED_SPEED  1.34f
#define K_GAIN     2.0f
#define ALPHA      10.66f
#define PED_RADIUS 0.3f
#define PED_MASS   60.0f
#define BETTA      0.71f
#define DT         0.4f
#define COST_A     1.0f
#define COST_B     1.0f
#define COST_E     1.0f
#define EPS        1e-8f

#define LOG2E      1.4426950408889634f
#define LOG2_ALPHA 3.4140815f

// Scratch: g_part[o * N + agent] = repulsive force on `agent` contributed by
// the unit pairing agent's tile with tile o. Each slot written exactly once.
__device__ float2 g_part[T * N];

__device__ __forceinline__ float fast_rsqrt(float x) {
    float y; asm("rsqrt.approx.ftz.f32 %0, %1;" : "=f"(y) : "f"(x)); return y;
}
__device__ __forceinline__ float fast_ex2(float x) {
    float y; asm("ex2.approx.ftz.f32 %0, %1;" : "=f"(y) : "f"(x)); return y;
}

__device__ __forceinline__ int tri_offset(int a) {   // first unit index of row a
    return 128 * a - (a * (a - 1)) / 2;
}

// ---------------- Phase A: symmetric pairwise repulsion ----------------
__global__ __launch_bounds__(1024, 1)
void phaseA_kernel(const float4* __restrict__ state)
{
    __shared__ float2 spos[N];   // 32 KB

    const int tid  = threadIdx.x;
    const int warp = tid >> 5;
    const int lane = tid & 31;

    #pragma unroll
    for (int k = 0; k < N / 1024; ++k) {
        const int j = tid + k * 1024;
        const float4 s = state[j];
        spos[j] = make_float2(s.x, s.y);
    }
    __syncthreads();

    const float cA  = -(1.0f / BETTA) * LOG2E;
    const float cB2 = (2.0f * PED_RADIUS / BETTA) * LOG2E + LOG2_ALPHA;

    // Transposed warp id: spreads the 2-unit warps evenly across blocks/SMs.
    const int g = warp * NBLK_A + blockIdx.x;

    #pragma unroll
    for (int rep = 0; rep < 2; ++rep) {
        const int u = g + rep * NWARPS_A;
        if (u >= NUNITS) break;

        // Triangular decode: u -> (a, b), a <= b
        int a = (int)(128.5f - sqrtf(fmaf(-2.0f, (float)u, 128.5f * 128.5f)));
        while (tri_offset(a + 1) <= u) ++a;
        while (tri_offset(a) > u) --a;
        const int b = a + (u - tri_offset(a));

        const float2 pa = spos[a * 32 + lane];
        const int bbase = b * 32;

        if (a == b) {
            // Diagonal: one-sided 32x32 (self-step contributes exactly 0)
            float fax = 0.0f, fay = 0.0f;
            #pragma unroll 4
            for (int k = 0; k < 32; ++k) {
                const int m = (lane - k) & 31;
                const float2 pb = spos[bbase + m];
                const float dx = pa.x - pb.x;
                const float dy = pa.y - pb.y;
                const float d2 = fmaf(dx, dx, fmaf(dy, dy, EPS));
                const float rs = fast_rsqrt(d2);
                const float d  = d2 * rs;
                const float e  = fast_ex2(fmaf(d, cA, cB2));
                const float c  = e * rs;
                fax = fmaf(c, dx, fax);
                fay = fmaf(c, dy, fay);
            }
            g_part[a * N + a * 32 + lane] = make_float2(fax, fay);
        } else {
            // Off-diagonal: symmetric. fa accumulates per-lane (tile a);
            // gb rotates with the b-agent it currently represents.
            float fax = 0.0f, fay = 0.0f;
            float gbx = 0.0f, gby = 0.0f;
            const int src = (lane + 31) & 31;   // receive from lane-1
            #pragma unroll 4
            for (int k = 0; k < 32; ++k) {
                const int m = (lane - k) & 31;       // b-agent handled this step
                const float2 pb = spos[bbase + m];
                const float dx = pa.x - pb.x;
                const float dy = pa.y - pb.y;
                const float d2 = fmaf(dx, dx, fmaf(dy, dy, EPS));
                const float rs = fast_rsqrt(d2);
                const float d  = d2 * rs;
                const float e  = fast_ex2(fmaf(d, cA, cB2));
                const float c  = e * rs;
                fax = fmaf(c, dx, fax);
                fay = fmaf(c, dy, fay);
                gbx = fmaf(-c, dx, gbx);             // force on b-agent m
                gby = fmaf(-c, dy, gby);
                // rotate gb so lane l next holds agent (l-(k+1))&31
                gbx = __shfl_sync(0xffffffffu, gbx, src);
                gby = __shfl_sync(0xffffffffu, gby, src);
            }
            // after 32 rotations gb is home: lane l holds agent b*32+l
            g_part[b * N + a * 32 + lane] = make_float2(fax, fay);
            g_part[a * N + bbase + lane]  = make_float2(gbx, gby);
        }
    }
}

// ---------------- Phase B: coalesced reduction + epilogue ----------------
// 4 threads per agent: thread q sums rows q*32..q*32+31 (coalesced across
// agents), then 2 shfl_xor steps combine (deterministic, rounding-identical
// on every lane). Same split for the robot rows. Epilogue on q==0.
__global__ __launch_bounds__(256)
void phaseB_kernel(const float4* __restrict__ state,
                   const float*  __restrict__ cost_in,
                   const float2* __restrict__ goals,
                   const float*  __restrict__ robot_init_pose,
                   const float4* __restrict__ observed,
                   float4* __restrict__ out,
                   float*  __restrict__ cost_out)
{
    const int tg    = blockIdx.x * blockDim.x + threadIdx.x;  // 0 .. 4*N-1
    const int agent = tg >> 2;
    const int q     = tg & 3;
    if (agent >= N) return;

    // own repulsive force: 32 coalesced independent loads
    float fx = 0.0f, fy = 0.0f;
    #pragma unroll 8
    for (int k = 0; k < 32; ++k) {
        const float2 p = g_part[(q * 32 + k) * N + agent];
        fx += p.x; fy += p.y;
    }
    // robot rows, same split (broadcast addresses -> L1 hits)
    float Rfx = 0.0f, Rfy = 0.0f;
    #pragma unroll 8
    for (int k = 0; k < 32; ++k) {
        const float2 p = g_part[(q * 32 + k) * N];
        Rfx += p.x; Rfy += p.y;
    }

    // combine 4 partials (commutative-rounding-identical on all lanes)
    fx  += __shfl_xor_sync(0xffffffffu, fx, 1);
    fy  += __shfl_xor_sync(0xffffffffu, fy, 1);
    Rfx += __shfl_xor_sync(0xffffffffu, Rfx, 1);
    Rfy += __shfl_xor_sync(0xffffffffu, Rfy, 1);
    fx  += __shfl_xor_sync(0xffffffffu, fx, 2);
    fy  += __shfl_xor_sync(0xffffffffu, fy, 2);
    Rfx += __shfl_xor_sync(0xffffffffu, Rfx, 2);
    Rfy += __shfl_xor_sync(0xffffffffu, Rfy, 2);

    if (q != 0) return;
    const int i = agent;

    // robot new pose
    const float4 s0 = state[0];
    const float2 g0 = goals[0];
    float r0x, r0y;
    {
        const float tgx = g0.x - s0.x;
        const float tgy = g0.y - s0.y;
        const float inv_gd = fast_rsqrt(fmaf(tgx, tgx, fmaf(tgy, tgy, EPS)));
        const float Fx = Rfx + K_GAIN * PED_MASS * (PED_SPEED * tgx * inv_gd - s0.z);
        const float Fy = Rfy + K_GAIN * PED_MASS * (PED_SPEED * tgy * inv_gd - s0.w);
        float vnx = fmaf(Fx, DT / PED_MASS, s0.z);
        float vny = fmaf(Fy, DT / PED_MASS, s0.w);
        const float spd = sqrtf(fmaf(vnx, vnx, fmaf(vny, vny, EPS)));
        const float sc = fminf(1.0f, PED_SPEED / spd);
        vnx *= sc; vny *= sc;
        r0x = fmaf(vnx, DT, s0.x);
        r0y = fmaf(vny, DT, s0.y);
    }

    // this agent: attraction + propagation
    const float4 s = state[i];
    const float2 g = goals[i];
    const float tgx = g.x - s.x;
    const float tgy = g.y - s.y;
    const float inv_gd = fast_rsqrt(fmaf(tgx, tgx, fmaf(tgy, tgy, EPS)));
    const float Fx = fx + K_GAIN * PED_MASS * (PED_SPEED * tgx * inv_gd - s.z);
    const float Fy = fy + K_GAIN * PED_MASS * (PED_SPEED * tgy * inv_gd - s.w);

    float vnx = fmaf(Fx, DT / PED_MASS, s.z);
    float vny = fmaf(Fy, DT / PED_MASS, s.w);
    const float spd = sqrtf(fmaf(vnx, vnx, fmaf(vny, vny, EPS)));
    const float sc = fminf(1.0f, PED_SPEED / spd);
    vnx *= sc; vny *= sc;
    const float pnx = fmaf(vnx, DT, s.x);
    const float pny = fmaf(vny, DT, s.y);

    out[i] = make_float4(pnx, pny, vnx, vny);

    // cost
    const float ripx = robot_init_pose[0];
    const float ripy = robot_init_pose[1];
    const float gvx = g0.x - ripx;
    const float gvy = g0.y - ripy;
    const float gnorm = sqrtf(gvx * gvx + gvy * gvy) + EPS;
    const float pg = ((r0x - ripx) * gvx + (r0y - ripy) * gvy) / gnorm;

    const float ddx = pnx - r0x;
    const float ddy = pny - r0y;
    const float dist = sqrtf(fmaf(ddx, ddx, fmaf(ddy, ddy, EPS)));
    const float blame = COST_B * fast_ex2(-dist * (LOG2E / COST_E));

    const float4 obs = observed[i];
    const float ox = pnx - obs.x;
    const float oy = pny - obs.y;
    const float dev = fmaf(ox, ox, oy * oy);

    cost_out[i] = cost_in[i] + (-COST_A * pg + blame + dev);
}

extern "C" void kernel_launch(void* const* d_in, const int* in_sizes, int n_in,
                              void* d_out, int out_size)
{
    const float4* state    = (const float4*)d_in[0];
    const float*  cost_in  = (const float*) d_in[1];
    const float2* goals    = (const float2*)d_in[2];
    const float*  rip      = (const float*) d_in[3];
    const float4* observed = (const float4*)d_in[4];

    float4* out_state = (float4*)d_out;
    float*  cost_out  = (float*)d_out + (size_t)N * 4;

    phaseA_kernel<<<NBLK_A, 1024>>>(state);
    phaseB_kernel<<<(4 * N) / 256, 256>>>(state, cost_in, goals, rip, observed,
                                          out_state, cost_out);
}

// round 13
// speedup vs baseline: 1.3545x; 1.1175x over previous
#include <cuda_runtime.h>

#define N 4096
#define T 128                  // tiles of 32 agents
#define NUNITS 8256            // T*(T+1)/2 unordered tile pairs incl diagonal

#define PED_SPEED  1.34f
#define K_GAIN     2.0f
#define ALPHA      10.66f
#define PED_RADIUS 0.3f
#define PED_MASS   60.0f
#define BETTA      0.71f
#define DT         0.4f
#define COST_A     1.0f
#define COST_B     1.0f
#define COST_E     1.0f
#define EPS        1e-8f

#define LOG2E      1.4426950408889634f
#define LOG2_ALPHA 3.4140815f

// Scratch: g_part[row * N + agent] = force on `agent` from tile `row`.
// Every slot written exactly once per launch (no atomics, deterministic).
__device__ float2 g_part[T * N];
// Monotonic barrier ticket. Each launch adds exactly gridDim.x arrivals, so
// target = (old/G + 1)*G works across correctness run + every graph replay
// with no reset required.
__device__ unsigned long long g_bar = 0ULL;

__device__ __forceinline__ float fast_rsqrt(float x) {
    float y; asm("rsqrt.approx.ftz.f32 %0, %1;" : "=f"(y) : "f"(x)); return y;
}
__device__ __forceinline__ float fast_ex2(float x) {
    float y; asm("ex2.approx.ftz.f32 %0, %1;" : "=f"(y) : "f"(x)); return y;
}
__device__ __forceinline__ int tri_offset(int a) {   // first unit of row a
    return 128 * a - (a * (a - 1)) / 2;
}

__global__ __launch_bounds__(1024, 1)
void fused_persistent(const float4* __restrict__ state,
                      const float*  __restrict__ cost_in,
                      const float2* __restrict__ goals,
                      const float*  __restrict__ robot_init_pose,
                      const float4* __restrict__ observed,
                      float4* __restrict__ out,
                      float*  __restrict__ cost_out)
{
    __shared__ float2 spos[N];        // 32 KB; reused as reduction scratch later

    const int tid  = threadIdx.x;
    const int warp = tid >> 5;
    const int lane = tid & 31;
    const int G    = gridDim.x;

    // ---- Stage positions ----
    #pragma unroll
    for (int k = 0; k < N / 1024; ++k) {
        const int j = tid + k * 1024;
        const float4 s = state[j];
        spos[j] = make_float2(s.x, s.y);
    }
    __syncthreads();

    const float cA  = -(1.0f / BETTA) * LOG2E;
    const float cB2 = (2.0f * PED_RADIUS / BETTA) * LOG2E + LOG2_ALPHA;

    // ================= Phase A: symmetric pair forces =================
    for (int u = warp * G + blockIdx.x; u < NUNITS; u += G * 32) {
        // Triangular decode u -> (a, b), a <= b
        int a = (int)(128.5f - sqrtf(fmaf(-2.0f, (float)u, 128.5f * 128.5f)));
        while (tri_offset(a + 1) <= u) ++a;
        while (tri_offset(a) > u) --a;
        const int b = a + (u - tri_offset(a));

        const float2 pa = spos[a * 32 + lane];
        const int bbase = b * 32;

        if (a == b) {
            float fax = 0.0f, fay = 0.0f;
            #pragma unroll 4
            for (int k = 0; k < 32; ++k) {
                const int m = (lane - k) & 31;
                const float2 pb = spos[bbase + m];
                const float dx = pa.x - pb.x;
                const float dy = pa.y - pb.y;
                const float d2 = fmaf(dx, dx, fmaf(dy, dy, EPS));
                const float rs = fast_rsqrt(d2);
                const float d  = d2 * rs;
                const float e  = fast_ex2(fmaf(d, cA, cB2));
                const float c  = e * rs;
                fax = fmaf(c, dx, fax);
                fay = fmaf(c, dy, fay);
            }
            g_part[a * N + a * 32 + lane] = make_float2(fax, fay);
        } else {
            float fax = 0.0f, fay = 0.0f;
            float gbx = 0.0f, gby = 0.0f;
            const int src = (lane + 31) & 31;
            #pragma unroll 4
            for (int k = 0; k < 32; ++k) {
                const int m = (lane - k) & 31;
                const float2 pb = spos[bbase + m];
                const float dx = pa.x - pb.x;
                const float dy = pa.y - pb.y;
                const float d2 = fmaf(dx, dx, fmaf(dy, dy, EPS));
                const float rs = fast_rsqrt(d2);
                const float d  = d2 * rs;
                const float e  = fast_ex2(fmaf(d, cA, cB2));
                const float c  = e * rs;
                fax = fmaf(c, dx, fax);
                fay = fmaf(c, dy, fay);
                gbx = fmaf(-c, dx, gbx);
                gby = fmaf(-c, dy, gby);
                gbx = __shfl_sync(0xffffffffu, gbx, src);
                gby = __shfl_sync(0xffffffffu, gby, src);
            }
            g_part[b * N + a * 32 + lane] = make_float2(fax, fay);
            g_part[a * N + bbase + lane]  = make_float2(gbx, gby);
        }
    }

    // ================= Device-wide barrier =================
    __threadfence();             // release g_part stores
    __syncthreads();
    if (tid == 0) {
        const unsigned long long old = atomicAdd(&g_bar, 1ULL);
        const unsigned long long target =
            (old / (unsigned long long)G + 1ULL) * (unsigned long long)G;
        unsigned long long v;
        do {
            asm volatile("ld.global.acquire.gpu.u64 %0, [%1];"
                         : "=l"(v) : "l"(&g_bar));
        } while (v < target);
        __threadfence();         // acquire: order subsequent g_part reads
    }
    __syncthreads();

    // ================= Phase B: per-tile reduction + epilogue =================
    // Reuse spos as scratch (positions no longer needed; per-block shared).
    float2* const s_red = spos;          // [32 warps][32 agents] = 8 KB
    float2* const s_rob = spos + 1024;   // [128] robot rows

    // Robot rows staged once (same for every tile).
    if (tid < T) s_rob[tid] = g_part[tid * N];

    for (int t = blockIdx.x; t < T; t += G) {
        __syncthreads();                 // s_rob ready / previous s_red consumed

        // warp w sums rows 4w..4w+3 for the 32 agents of tile t (coalesced)
        {
            float fx = 0.0f, fy = 0.0f;
            #pragma unroll
            for (int k = 0; k < 4; ++k) {
                const float2 p = g_part[(warp * 4 + k) * N + t * 32 + lane];
                fx += p.x; fy += p.y;
            }
            s_red[warp * 32 + lane] = make_float2(fx, fy);
        }
        __syncthreads();

        if (tid < 32) {
            const int i = t * 32 + tid;

            float fx = 0.0f, fy = 0.0f;
            #pragma unroll 8
            for (int w = 0; w < 32; ++w) {
                const float2 p = s_red[w * 32 + tid];
                fx += p.x; fy += p.y;
            }

            float Rfx = 0.0f, Rfy = 0.0f;
            #pragma unroll 8
            for (int r = 0; r < T; ++r) { Rfx += s_rob[r].x; Rfy += s_rob[r].y; }

            // robot new pose
            const float4 s0 = state[0];
            const float2 g0 = goals[0];
            float r0x, r0y;
            {
                const float tgx = g0.x - s0.x;
                const float tgy = g0.y - s0.y;
                const float inv_gd = fast_rsqrt(fmaf(tgx, tgx, fmaf(tgy, tgy, EPS)));
                const float Fx = Rfx + K_GAIN * PED_MASS * (PED_SPEED * tgx * inv_gd - s0.z);
                const float Fy = Rfy + K_GAIN * PED_MASS * (PED_SPEED * tgy * inv_gd - s0.w);
                float vnx = fmaf(Fx, DT / PED_MASS, s0.z);
                float vny = fmaf(Fy, DT / PED_MASS, s0.w);
                const float spd = sqrtf(fmaf(vnx, vnx, fmaf(vny, vny, EPS)));
                const float sc = fminf(1.0f, PED_SPEED / spd);
                vnx *= sc; vny *= sc;
                r0x = fmaf(vnx, DT, s0.x);
                r0y = fmaf(vny, DT, s0.y);
            }

            // this agent: attraction + propagation
            const float4 s = state[i];
            const float2 g = goals[i];
            const float tgx = g.x - s.x;
            const float tgy = g.y - s.y;
            const float inv_gd = fast_rsqrt(fmaf(tgx, tgx, fmaf(tgy, tgy, EPS)));
            const float Fx = fx + K_GAIN * PED_MASS * (PED_SPEED * tgx * inv_gd - s.z);
            const float Fy = fy + K_GAIN * PED_MASS * (PED_SPEED * tgy * inv_gd - s.w);

            float vnx = fmaf(Fx, DT / PED_MASS, s.z);
            float vny = fmaf(Fy, DT / PED_MASS, s.w);
            const float spd = sqrtf(fmaf(vnx, vnx, fmaf(vny, vny, EPS)));
            const float sc = fminf(1.0f, PED_SPEED / spd);
            vnx *= sc; vny *= sc;
            const float pnx = fmaf(vnx, DT, s.x);
            const float pny = fmaf(vny, DT, s.y);

            out[i] = make_float4(pnx, pny, vnx, vny);

            // cost
            const float ripx = robot_init_pose[0];
            const float ripy = robot_init_pose[1];
            const float gvx = g0.x - ripx;
            const float gvy = g0.y - ripy;
            const float gnorm = sqrtf(gvx * gvx + gvy * gvy) + EPS;
            const float pg = ((r0x - ripx) * gvx + (r0y - ripy) * gvy) / gnorm;

            const float ddx = pnx - r0x;
            const float ddy = pny - r0y;
            const float dist = sqrtf(fmaf(ddx, ddx, fmaf(ddy, ddy, EPS)));
            const float blame = COST_B * fast_ex2(-dist * (LOG2E / COST_E));

            const float4 obs = observed[i];
            const float ox = pnx - obs.x;
            const float oy = pny - obs.y;
            const float dev = fmaf(ox, ox, oy * oy);

            cost_out[i] = cost_in[i] + (-COST_A * pg + blame + dev);
        }
    }
}

extern "C" void kernel_launch(void* const* d_in, const int* in_sizes, int n_in,
                              void* d_out, int out_size)
{
    const float4* state    = (const float4*)d_in[0];
    const float*  cost_in  = (const float*) d_in[1];
    const float2* goals    = (const float2*)d_in[2];
    const float*  rip      = (const float*) d_in[3];
    const float4* observed = (const float4*)d_in[4];

    float4* out_state = (float4*)d_out;
    float*  cost_out  = (float*)d_out + (size_t)N * 4;

    // One 1024-thread block per SM: all blocks co-resident (1 block/SM fits:
    // <=64 regs, ~33 KB smem), so the spin barrier cannot deadlock.
    int nsm = 0;
    if (cudaDeviceGetAttribute(&nsm, cudaDevAttrMultiProcessorCount, 0) != cudaSuccess
        || nsm <= 0) nsm = 148;
    if (nsm > 1024) nsm = 1024;

    fused_persistent<<<nsm, 1024>>>(state, cost_in, goals, rip, observed,
                                    out_state, cost_out);
}

// round 14
// speedup vs baseline: 1.5613x; 1.1527x over previous
#include <cuda_runtime.h>

#define N 4096
#define T 128                 // tiles of 32 agents
#define NUNITS 8256           // T*(T+1)/2 unordered tile pairs incl diagonal
#define NBLK_A 152
#define NWARPS_A (NBLK_A * 32)   // 4864

#define PED_SPEED  1.34f
#define K_GAIN     2.0f
#define ALPHA      10.66f
#define PED_RADIUS 0.3f
#define PED_MASS   60.0f
#define BETTA      0.71f
#define DT         0.4f
#define COST_A     1.0f
#define COST_B     1.0f
#define COST_E     1.0f
#define EPS        1e-8f

#define LOG2E      1.4426950408889634f
#define LOG2_ALPHA 3.4140815f

// Scratch: g_part[(a*T + o)*32 + lane] = force on agent a*32+lane from tile o.
// Tile a's 128 partial rows are one contiguous 32 KB chunk. Every slot written
// exactly once per launch (no atomics, deterministic).
__device__ float2 g_part[T * T * 32];

__device__ __forceinline__ float fast_rsqrt(float x) {
    float y; asm("rsqrt.approx.ftz.f32 %0, %1;" : "=f"(y) : "f"(x)); return y;
}
__device__ __forceinline__ float fast_ex2(float x) {
    float y; asm("ex2.approx.ftz.f32 %0, %1;" : "=f"(y) : "f"(x)); return y;
}
__device__ __forceinline__ int tri_offset(int a) {   // first unit index of row a
    return 128 * a - (a * (a - 1)) / 2;
}

// ---------------- Phase A: symmetric pairwise repulsion (R11-proven) --------
__global__ __launch_bounds__(1024, 1)
void phaseA_kernel(const float4* __restrict__ state)
{
    __shared__ float2 spos[N];   // 32 KB

    const int tid  = threadIdx.x;
    const int warp = tid >> 5;
    const int lane = tid & 31;

    #pragma unroll
    for (int k = 0; k < N / 1024; ++k) {
        const int j = tid + k * 1024;
        const float4 s = state[j];
        spos[j] = make_float2(s.x, s.y);
    }
    __syncthreads();

    const float cA  = -(1.0f / BETTA) * LOG2E;
    const float cB2 = (2.0f * PED_RADIUS / BETTA) * LOG2E + LOG2_ALPHA;

    // Transposed warp id: spreads the 2-unit warps evenly across blocks/SMs.
    const int g = warp * NBLK_A + blockIdx.x;

    #pragma unroll
    for (int rep = 0; rep < 2; ++rep) {
        const int u = g + rep * NWARPS_A;
        if (u >= NUNITS) break;

        // Triangular decode: u -> (a, b), a <= b
        int a = (int)(128.5f - sqrtf(fmaf(-2.0f, (float)u, 128.5f * 128.5f)));
        while (tri_offset(a + 1) <= u) ++a;
        while (tri_offset(a) > u) --a;
        const int b = a + (u - tri_offset(a));

        const float2 pa = spos[a * 32 + lane];
        const int bbase = b * 32;

        if (a == b) {
            // Diagonal: one-sided 32x32 (self-step contributes exactly 0)
            float fax = 0.0f, fay = 0.0f;
            #pragma unroll 4
            for (int k = 0; k < 32; ++k) {
                const int m = (lane - k) & 31;
                const float2 pb = spos[bbase + m];
                const float dx = pa.x - pb.x;
                const float dy = pa.y - pb.y;
                const float d2 = fmaf(dx, dx, fmaf(dy, dy, EPS));
                const float rs = fast_rsqrt(d2);
                const float d  = d2 * rs;
                const float e  = fast_ex2(fmaf(d, cA, cB2));
                const float c  = e * rs;
                fax = fmaf(c, dx, fax);
                fay = fmaf(c, dy, fay);
            }
            g_part[(a * T + b) * 32 + lane] = make_float2(fax, fay);
        } else {
            // Off-diagonal: symmetric. fa per-lane (tile a); gb rotates.
            float fax = 0.0f, fay = 0.0f;
            float gbx = 0.0f, gby = 0.0f;
            const int src = (lane + 31) & 31;   // receive from lane-1
            #pragma unroll 4
            for (int k = 0; k < 32; ++k) {
                const int m = (lane - k) & 31;       // b-agent handled this step
                const float2 pb = spos[bbase + m];
                const float dx = pa.x - pb.x;
                const float dy = pa.y - pb.y;
                const float d2 = fmaf(dx, dx, fmaf(dy, dy, EPS));
                const float rs = fast_rsqrt(d2);
                const float d  = d2 * rs;
                const float e  = fast_ex2(fmaf(d, cA, cB2));
                const float c  = e * rs;
                fax = fmaf(c, dx, fax);
                fay = fmaf(c, dy, fay);
                gbx = fmaf(-c, dx, gbx);             // force on b-agent m
                gby = fmaf(-c, dy, gby);
                gbx = __shfl_sync(0xffffffffu, gbx, src);
                gby = __shfl_sync(0xffffffffu, gby, src);
            }
            // after 32 rotations gb is home: lane l holds agent b*32+l
            g_part[(a * T + b) * 32 + lane] = make_float2(fax, fay);
            g_part[(b * T + a) * 32 + lane] = make_float2(gbx, gby);
        }
    }
}

// ---------------- Phase B: one block per tile ----------------
// Block t: 8 warps, warp w sums rows w*16..w*16+15 of tile t's contiguous
// 32 KB chunk (coalesced, L2-hot), shared tree, epilogue on warp 0.
__global__ __launch_bounds__(256)
void phaseB_kernel(const float4* __restrict__ state,
                   const float*  __restrict__ cost_in,
                   const float2* __restrict__ goals,
                   const float*  __restrict__ robot_init_pose,
                   const float4* __restrict__ observed,
                   float4* __restrict__ out,
                   float*  __restrict__ cost_out)
{
    __shared__ float2 s_red[8 * 32];   // per-warp partial per agent
    __shared__ float2 s_rob[T];        // robot partial rows

    const int t    = blockIdx.x;       // tile 0..127
    const int tid  = threadIdx.x;
    const int warp = tid >> 5;
    const int lane = tid & 31;

    // Stage robot rows: part[(0*T + o)*32 + 0], o = tid (256 threads >= 128)
    if (tid < T) s_rob[tid] = g_part[tid * 32];

    // Warp w: sum 16 coalesced rows for this tile's 32 agents
    {
        const float2* base = &g_part[(t * T + warp * 16) * 32];
        float fx = 0.0f, fy = 0.0f;
        #pragma unroll
        for (int k = 0; k < 16; ++k) {
            const float2 p = base[k * 32 + lane];
            fx += p.x; fy += p.y;
        }
        s_red[warp * 32 + lane] = make_float2(fx, fy);
    }
    __syncthreads();

    if (warp == 0) {
        const int i = t * 32 + lane;

        // own force: fixed-order sum of the 8 warp partials
        float fx = 0.0f, fy = 0.0f;
        #pragma unroll
        for (int w = 0; w < 8; ++w) {
            const float2 p = s_red[w * 32 + lane];
            fx += p.x; fy += p.y;
        }

        // robot force: fixed-order sum of 128 rows (identical on all lanes)
        float Rfx = 0.0f, Rfy = 0.0f;
        #pragma unroll 8
        for (int o = 0; o < T; ++o) { Rfx += s_rob[o].x; Rfy += s_rob[o].y; }

        // robot new pose
        const float4 s0 = state[0];
        const float2 g0 = goals[0];
        float r0x, r0y;
        {
            const float tgx = g0.x - s0.x;
            const float tgy = g0.y - s0.y;
            const float inv_gd = fast_rsqrt(fmaf(tgx, tgx, fmaf(tgy, tgy, EPS)));
            const float Fx = Rfx + K_GAIN * PED_MASS * (PED_SPEED * tgx * inv_gd - s0.z);
            const float Fy = Rfy + K_GAIN * PED_MASS * (PED_SPEED * tgy * inv_gd - s0.w);
            float vnx = fmaf(Fx, DT / PED_MASS, s0.z);
            float vny = fmaf(Fy, DT / PED_MASS, s0.w);
            const float spd = sqrtf(fmaf(vnx, vnx, fmaf(vny, vny, EPS)));
            const float sc = fminf(1.0f, PED_SPEED / spd);
            vnx *= sc; vny *= sc;
            r0x = fmaf(vnx, DT, s0.x);
            r0y = fmaf(vny, DT, s0.y);
        }

        // this agent: attraction + propagation
        const float4 s = state[i];
        const float2 g = goals[i];
        const float tgx = g.x - s.x;
        const float tgy = g.y - s.y;
        const float inv_gd = fast_rsqrt(fmaf(tgx, tgx, fmaf(tgy, tgy, EPS)));
        const float Fx = fx + K_GAIN * PED_MASS * (PED_SPEED * tgx * inv_gd - s.z);
        const float Fy = fy + K_GAIN * PED_MASS * (PED_SPEED * tgy * inv_gd - s.w);

        float vnx = fmaf(Fx, DT / PED_MASS, s.z);
        float vny = fmaf(Fy, DT / PED_MASS, s.w);
        const float spd = sqrtf(fmaf(vnx, vnx, fmaf(vny, vny, EPS)));
        const float sc = fminf(1.0f, PED_SPEED / spd);
        vnx *= sc; vny *= sc;
        const float pnx = fmaf(vnx, DT, s.x);
        const float pny = fmaf(vny, DT, s.y);

        out[i] = make_float4(pnx, pny, vnx, vny);

        // cost
        const float ripx = robot_init_pose[0];
        const float ripy = robot_init_pose[1];
        const float gvx = g0.x - ripx;
        const float gvy = g0.y - ripy;
        const float gnorm = sqrtf(gvx * gvx + gvy * gvy) + EPS;
        const float pg = ((r0x - ripx) * gvx + (r0y - ripy) * gvy) / gnorm;

        const float ddx = pnx - r0x;
        const float ddy = pny - r0y;
        const float dist = sqrtf(fmaf(ddx, ddx, fmaf(ddy, ddy, EPS)));
        const float blame = COST_B * fast_ex2(-dist * (LOG2E / COST_E));

        const float4 obs = observed[i];
        const float ox = pnx - obs.x;
        const float oy = pny - obs.y;
        const float dev = fmaf(ox, ox, oy * oy);

        cost_out[i] = cost_in[i] + (-COST_A * pg + blame + dev);
    }
}

extern "C" void kernel_launch(void* const* d_in, const int* in_sizes, int n_in,
                              void* d_out, int out_size)
{
    const float4* state    = (const float4*)d_in[0];
    const float*  cost_in  = (const float*) d_in[1];
    const float2* goals    = (const float2*)d_in[2];
    const float*  rip      = (const float*) d_in[3];
    const float4* observed = (const float4*)d_in[4];

    float4* out_state = (float4*)d_out;
    float*  cost_out  = (float*)d_out + (size_t)N * 4;

    phaseA_kernel<<<NBLK_A, 1024>>>(state);
    phaseB_kernel<<<T, 256>>>(state, cost_in, goals, rip, observed,
                              out_state, cost_out);
}